// round 14
// baseline (speedup 1.0000x reference)
#include <cuda_runtime.h>
#include <math.h>

#define IMG   512
#define PIX   (IMG * IMG)
#define NIMG  64
#define TX    128
#define RPB   64
#define NITER (RPB + 10)            // 74 streamed rows per block
#define NPAIR (NITER / 2)           // 37 row pairs
#define WCH   40                    // float2 chunks per row array (80 floats)
#define GX    2                     // 2 col strips of 256
#define GY    (IMG / RPB)           // 8
#define GZ    NIMG                  // 64 images
#define NBLK  (GX * GY * GZ)        // 1024

typedef unsigned long long u64;

__device__ double g_part[NBLK];
__device__ int    g_cnt;            // zero-initialized; self-resets each launch

static __device__ __forceinline__ u64 pk2(float a, float b) {
    u64 r; asm("mov.b64 %0, {%1, %2};" : "=l"(r) : "f"(a), "f"(b)); return r;
}
static __device__ __forceinline__ void unpk2(u64 v, float& a, float& b) {
    asm("mov.b64 {%0, %1}, %2;" : "=f"(a), "=f"(b) : "l"(v));
}
static __device__ __forceinline__ u64 f2add(u64 a, u64 b) {
    u64 d; asm("add.rn.f32x2 %0, %1, %2;" : "=l"(d) : "l"(a), "l"(b)); return d;
}
static __device__ __forceinline__ u64 f2sub(u64 a, u64 b) {
    u64 d; asm("sub.rn.f32x2 %0, %1, %2;" : "=l"(d) : "l"(a), "l"(b)); return d;
}
static __device__ __forceinline__ u64 f2mul(u64 a, u64 b) {
    u64 d; asm("mul.rn.f32x2 %0, %1, %2;" : "=l"(d) : "l"(a), "l"(b)); return d;
}
static __device__ __forceinline__ u64 f2fma(u64 a, u64 b, u64 c) {
    u64 d; asm("fma.rn.f32x2 %0, %1, %2, %3;" : "=l"(d) : "l"(a), "l"(b), "l"(c)); return d;
}

__global__ void __launch_bounds__(TX, 3) ssim_main(
    const float* __restrict__ pred, const float* __restrict__ gt,
    float* __restrict__ out)
{
    // COLUMN-PAIR packing: each f32x2 lane = 2 adjacent columns of ONE image
    // (was: 2 images). Warp tile = scalar u-plane + v-plane (u=p+g, v=p-g),
    // so adjacent outputs SHARE overlapping taps: 7 LDS.64/plane/row (112B)
    // instead of 11 LDS.128 (176B) per thread-row -> L1 bytes -36%.
    // Odd-offset taps are formed with pk2() register pairs (alu pipe, idle).
    // Ring, vblur, epilogue algebra identical to R13.
    __shared__ float2 su[TX / 32][2][2][WCH];   // [warp][buf][row][chunk]
    __shared__ float2 sv[TX / 32][2][2][WCH];
    __shared__ float wred[TX / 32];
    __shared__ int   slast;

    const int tid  = threadIdx.x;
    const int wpid = tid >> 5;
    const int lane = tid & 31;
    const int W    = blockIdx.x * 256 + wpid * 64;   // warp's first output col
    const int ry0  = blockIdx.y * RPB;
    const int img  = blockIdx.z;

    const float* pim = pred + (size_t)img * PIX;
    const float* gim = gt   + (size_t)img * PIX;

    // Gaussian 1D weights (sigma = 11/6, normalized) — same math as reference
    float w[6];
    {
        const float sig = 11.0f / 6.0f;
        const float inv = 1.0f / (2.0f * sig * sig);
        float e[6];
        #pragma unroll
        for (int d = 0; d < 6; ++d) e[d] = expf(-(float)(d * d) * inv);
        float s = e[0] + 2.f * (e[1] + e[2] + e[3] + e[4] + e[5]);
        #pragma unroll
        for (int d = 0; d < 6; ++d) w[d] = e[d] / s;
    }
    u64 w2[6];
    #pragma unroll
    for (int d = 0; d < 6; ++d) w2[d] = pk2(w[d], w[d]);

    const float C1 = 0.01f * 0.01f;
    const float C2 = 0.03f * 0.03f;
    const u64 c1_2  = pk2(C1, C1);
    const u64 c2_2  = pk2(C2, C2);
    const u64 half2 = pk2(0.5f, 0.5f);

    // 11-row ring buffers of horizontally-blurred channels (registers)
    u64 rU[11], rV[11], rUU[11], rVV[11];
    u64 acc0 = 0ull, acc1 = 0ull;

    // main chunk: cols (W-8+2l, W-8+2l+1); halo (lanes 0-7): cols W+56+2l..
    const int cm = W - 8 + 2 * lane;
    const int ch = W + 56 + 2 * lane;
    const bool hl = (lane < 8);

    float2 pmA, gmA, phA, ghA;
    float2 pmB, gmB, phB, ghB;

    #define LOADROW(sfx, T)                                                     \
        {                                                                       \
            const int yin = ry0 - 5 + (T);                                      \
            const bool rok = ((unsigned)yin < IMG);                             \
            const float2 z2 = make_float2(0.f, 0.f);                            \
            const bool okm = rok && ((unsigned)cm < IMG);                       \
            pm##sfx = okm ? *(const float2*)(pim + yin * IMG + cm) : z2;        \
            gm##sfx = okm ? *(const float2*)(gim + yin * IMG + cm) : z2;        \
            const bool okh = rok && hl && ((unsigned)ch < IMG);                 \
            ph##sfx = okh ? *(const float2*)(pim + yin * IMG + ch) : z2;        \
            gh##sfx = okh ? *(const float2*)(gim + yin * IMG + ch) : z2;        \
        }

    LOADROW(A, 0)
    LOADROW(B, 1)

    for (int outer = 0; outer < 4; ++outer) {
        #pragma unroll
        for (int j = 0; j < 11; ++j) {
            const int pair = outer * 11 + j;
            if (pair < NPAIR) {
                const int buf = pair & 1;
                // ---- store u/v planes (transform transient at STS) ----
                su[wpid][buf][0][lane] = make_float2(pmA.x + gmA.x, pmA.y + gmA.y);
                sv[wpid][buf][0][lane] = make_float2(pmA.x - gmA.x, pmA.y - gmA.y);
                su[wpid][buf][1][lane] = make_float2(pmB.x + gmB.x, pmB.y + gmB.y);
                sv[wpid][buf][1][lane] = make_float2(pmB.x - gmB.x, pmB.y - gmB.y);
                if (hl) {
                    su[wpid][buf][0][32 + lane] = make_float2(phA.x + ghA.x, phA.y + ghA.y);
                    sv[wpid][buf][0][32 + lane] = make_float2(phA.x - ghA.x, phA.y - ghA.y);
                    su[wpid][buf][1][32 + lane] = make_float2(phB.x + ghB.x, phB.y + ghB.y);
                    sv[wpid][buf][1][32 + lane] = make_float2(phB.x - ghB.x, phB.y - ghB.y);
                }
                // ---- prefetch next pair (warp-local; no block barrier) ----
                const int t0 = 2 * pair;
                if (t0 + 2 < NITER) LOADROW(A, t0 + 2)
                if (t0 + 3 < NITER) LOADROW(B, t0 + 3)
                __syncwarp();

                const int k0 = (2 * j) % 11;
                const int k1 = (2 * j + 1) % 11;

                // per-plane hblur: 7 LDS.64 -> floats [2l+2 .. 2l+15];
                // output cols (W+2l, W+2l+1) = tile floats (2l+8, 2l+9).
                #define HPLANE(PL, ROW, hM, hS)                                             \
                    {                                                                       \
                        const float2* q = &PL[wpid][buf][ROW][lane + 1];                    \
                        float2 q0 = q[0], q1 = q[1], q2 = q[2], q3 = q[3];                  \
                        float2 q4 = q[4], q5 = q[5], q6 = q[6];                             \
                        u64 T0 = pk2(q3.x, q3.y);                                           \
                        hM = f2mul(T0, w2[0]);                                              \
                        hS = f2mul(f2mul(T0, T0), w2[0]);                                   \
                        { u64 TL = pk2(q2.y, q3.x), TR = pk2(q3.y, q4.x);                   \
                          hM = f2fma(f2add(TL, TR), w2[1], hM);                             \
                          hS = f2fma(f2fma(TR, TR, f2mul(TL, TL)), w2[1], hS); }            \
                        { u64 TL = pk2(q2.x, q2.y), TR = pk2(q4.x, q4.y);                   \
                          hM = f2fma(f2add(TL, TR), w2[2], hM);                             \
                          hS = f2fma(f2fma(TR, TR, f2mul(TL, TL)), w2[2], hS); }            \
                        { u64 TL = pk2(q1.y, q2.x), TR = pk2(q4.y, q5.x);                   \
                          hM = f2fma(f2add(TL, TR), w2[3], hM);                             \
                          hS = f2fma(f2fma(TR, TR, f2mul(TL, TL)), w2[3], hS); }            \
                        { u64 TL = pk2(q1.x, q1.y), TR = pk2(q5.x, q5.y);                   \
                          hM = f2fma(f2add(TL, TR), w2[4], hM);                             \
                          hS = f2fma(f2fma(TR, TR, f2mul(TL, TL)), w2[4], hS); }            \
                        { u64 TL = pk2(q0.y, q1.x), TR = pk2(q5.y, q6.x);                   \
                          hM = f2fma(f2add(TL, TR), w2[5], hM);                             \
                          hS = f2fma(f2fma(TR, TR, f2mul(TL, TL)), w2[5], hS); }            \
                    }
                #define HBLUR(ROW, KD)                                                      \
                    {                                                                       \
                        u64 hU, hUU, hV, hVV;                                               \
                        HPLANE(su, ROW, hU, hUU)                                            \
                        HPLANE(sv, ROW, hV, hVV)                                            \
                        rU[KD] = hU; rV[KD] = hV; rUU[KD] = hUU; rVV[KD] = hVV;             \
                    }
                HBLUR(0, k0)
                HBLUR(1, k1)
                #undef HBLUR
                #undef HPLANE

                if (pair >= 5) {
                    #define VS(K, JJ) (((K) + 6 + (JJ) + 11) % 11)
                    #define VBLUR(dst, r, K)                                           \
                        { u64 pa = f2fma(f2add(r[VS(K,-1)], r[VS(K,1)]), w2[1],        \
                                         f2mul(r[VS(K,0)], w2[0]));                    \
                          pa = f2fma(f2add(r[VS(K,-3)], r[VS(K,3)]), w2[3], pa);       \
                          u64 pb = f2mul(f2add(r[VS(K,-2)], r[VS(K,2)]), w2[2]);       \
                          pb = f2fma(f2add(r[VS(K,-4)], r[VS(K,4)]), w2[4], pb);       \
                          pb = f2fma(f2add(r[VS(K,-5)], r[VS(K,5)]), w2[5], pb);       \
                          dst = f2add(pa, pb); }
                    #define SSIMROW(K, ACC)                                            \
                        { u64 mU, mV, SU, SV;                                          \
                          VBLUR(mU, rU,  K); VBLUR(mV, rV,  K);                        \
                          VBLUR(SU, rUU, K); VBLUR(SV, rVV, K);                        \
                          u64 t1 = f2mul(mU, mU);                                      \
                          u64 t2 = f2mul(mV, mV);                                      \
                          u64 dm = f2sub(t1, t2);          /* 4 m1 m2 */               \
                          u64 sm = f2add(t1, t2);          /* 2(m1^2+m2^2) */          \
                          t1 = f2fma(dm, half2, c1_2);     /* A  */                    \
                          t2 = f2fma(f2sub(f2sub(SU, SV), dm), half2, c2_2); /* B */   \
                          u64 num = f2mul(t1, t2);                                     \
                          t1 = f2fma(sm, half2, c1_2);     /* Cq */                    \
                          t2 = f2fma(f2sub(f2add(SU, SV), sm), half2, c2_2); /* Dq */  \
                          u64 den = f2mul(t1, t2);                                     \
                          float na, nb, da, db;                                        \
                          unpk2(num, na, nb); unpk2(den, da, db);                      \
                          ACC = f2add(ACC, pk2(__fdividef(na, da),                     \
                                               __fdividef(nb, db))); }
                    SSIMROW(k0, acc0)
                    SSIMROW(k1, acc1)
                    #undef SSIMROW
                    #undef VBLUR
                    #undef VS
                }
            }
        }
    }
    #undef LOADROW

    // ---- block reduction (deterministic partials, no float atomics) ----
    u64 accT = f2add(acc0, acc1);
    float a0, a1; unpk2(accT, a0, a1);
    float s = a0 + a1;
    #pragma unroll
    for (int o = 16; o > 0; o >>= 1) s += __shfl_xor_sync(0xffffffffu, s, o);
    if (lane == 0) wred[wpid] = s;
    __syncthreads();
    if (tid == 0) {
        double bs = 0.0;
        #pragma unroll
        for (int i = 0; i < TX / 32; ++i) bs += (double)wred[i];
        const int bid = blockIdx.x + GX * (blockIdx.y + GY * blockIdx.z);
        g_part[bid] = bs;
        __threadfence();
        int old = atomicAdd(&g_cnt, 1);
        slast = (old == NBLK - 1) ? 1 : 0;
    }
    __syncthreads();

    // ---- last block finalizes (deterministic fixed-order double sum) ----
    if (slast) {
        __threadfence();
        double v = 0.0;
        #pragma unroll
        for (int i = 0; i < NBLK / TX; ++i)
            v += g_part[tid + i * TX];
        #pragma unroll
        for (int o = 16; o > 0; o >>= 1) v += __shfl_xor_sync(0xffffffffu, v, o);
        __shared__ double sh[TX / 32];
        if ((tid & 31) == 0) sh[tid >> 5] = v;
        __syncthreads();
        if (tid == 0) {
            double tot = 0.0;
            #pragma unroll
            for (int i = 0; i < TX / 32; ++i) tot += sh[i];
            out[0] = (float)(1.0 - tot / ((double)NIMG * (double)PIX));
            g_cnt = 0;   // self-reset for graph replay
        }
    }
}

extern "C" void kernel_launch(void* const* d_in, const int* in_sizes, int n_in,
                              void* d_out, int out_size)
{
    const float* pred = (const float*)d_in[0];
    const float* gt   = (const float*)d_in[1];
    float* out = (float*)d_out;

    dim3 grid(GX, GY, GZ);
    ssim_main<<<grid, TX>>>(pred, gt, out);
}